// round 11
// baseline (speedup 1.0000x reference)
#include <cuda_runtime.h>
#include <cuda_fp16.h>
#include <stdint.h>

#define TOKS 8192
#define DIMD 512
#define HIDH 1024
#define NEXP 16
#define ECAP 2048                    // fixed capacity per expert (mean 1024, >30 sigma)
#define HROWS (NEXP * ECAP)

// ---------------- device scratch (64-halves pad for tail prefetch/ldg) ----------------
__device__ int   g_cnt[NEXP];
__device__ int   g_tok[NEXP * ECAP];
__device__ float g_wgt[NEXP * ECAP];
__device__ __align__(256) __half g_xh[TOKS * DIMD + 64];             // x (fp16)
__device__ __align__(256) __half g_w1h[NEXP * HIDH * DIMD];          // W1^T: [e][h][d] fp16
__device__ __align__(256) __half g_w2h[NEXP * DIMD * HIDH];          // W2^T: [e][dout][h] fp16
__device__ __align__(256) __half g_hh[(size_t)HROWS * HIDH + 64];    // gelu hidden (fp16)

// ---------------- helpers ----------------
__device__ __forceinline__ uint32_t smem_u32(const void* p) {
    uint32_t a;
    asm("{ .reg .u64 t; cvta.to.shared.u64 t, %1; cvt.u32.u64 %0, t; }" : "=r"(a) : "l"(p));
    return a;
}
__device__ __forceinline__ void cpa16(uint32_t dst, const void* src, uint32_t sz) {
    asm volatile("cp.async.cg.shared.global [%0], [%1], 16, %2;"
                 :: "r"(dst), "l"(src), "r"(sz) : "memory");
}
__device__ __forceinline__ void cp_commit() {
    asm volatile("cp.async.commit_group;" ::: "memory");
}
template <int N>
__device__ __forceinline__ void cp_wait() {
    asm volatile("cp.async.wait_group %0;" :: "n"(N) : "memory");
}
__device__ __forceinline__ void ldsm4(uint32_t* r, uint32_t addr) {
    asm volatile("ldmatrix.sync.aligned.m8n8.x4.shared.b16 {%0,%1,%2,%3}, [%4];"
                 : "=r"(r[0]), "=r"(r[1]), "=r"(r[2]), "=r"(r[3]) : "r"(addr));
}
__device__ __forceinline__ void mma_f16(float* d, const uint32_t* a, const uint32_t* b) {
    asm volatile(
        "mma.sync.aligned.m16n8k16.row.col.f32.f16.f16.f32 "
        "{%0,%1,%2,%3}, {%4,%5,%6,%7}, {%8,%9}, {%0,%1,%2,%3};"
        : "+f"(d[0]), "+f"(d[1]), "+f"(d[2]), "+f"(d[3])
        : "r"(a[0]), "r"(a[1]), "r"(a[2]), "r"(a[3]), "r"(b[0]), "r"(b[1]));
}
__device__ __forceinline__ void pf_l1(const void* p) {
    asm volatile("prefetch.global.L1 [%0];" :: "l"(p));
}

// smem: s_tok[128] @0, s_wgt[128] @512, 5 B-stages @1024
// B stage (BK=64): 128 rows x 128B, SW128 (addr = row*128 + (t ^ ((row&7)*16)))
#define STG      16384
#define SM_STAGE 1024
#define SMEM_DYN (SM_STAGE + 5 * STG)   // 82944

extern __shared__ __align__(1024) char smc[];

// ---------------- prep kernels ----------------
__global__ void k_split_x(const float* __restrict__ x) {
    if (blockIdx.x == 0 && threadIdx.x < NEXP) g_cnt[threadIdx.x] = 0;
    int i = blockIdx.x * 256 + threadIdx.x;
    if (i < TOKS * DIMD / 4) {
        float4 v = ((const float4*)x)[i];
        ((__half2*)g_xh)[i * 2]     = __floats2half2_rn(v.x, v.y);
        ((__half2*)g_xh)[i * 2 + 1] = __floats2half2_rn(v.z, v.w);
    }
}

__global__ void k_scatter(const float* __restrict__ rt) {
    __shared__ int s_cnt[NEXP], s_base[NEXP];
    int tid = threadIdx.x;
    int n = blockIdx.x * 256 + tid;
    if (tid < NEXP) s_cnt[tid] = 0;
    __syncthreads();
    float v[NEXP];
    const float4* r4 = (const float4*)(rt + (size_t)n * NEXP);
    float4 a = r4[0], b = r4[1], c = r4[2], d = r4[3];
    v[0]=a.x; v[1]=a.y; v[2]=a.z; v[3]=a.w; v[4]=b.x; v[5]=b.y; v[6]=b.z; v[7]=b.w;
    v[8]=c.x; v[9]=c.y; v[10]=c.z; v[11]=c.w; v[12]=d.x; v[13]=d.y; v[14]=d.z; v[15]=d.w;
    int le[4]; float lv[4]; int ls[4]; int k = 0;
    #pragma unroll
    for (int e = 0; e < NEXP; ++e)
        if (v[e] > 0.0f && k < 4) { le[k] = e; lv[k] = v[e]; ls[k] = atomicAdd(&s_cnt[e], 1); ++k; }
    __syncthreads();
    if (tid < NEXP) s_base[tid] = atomicAdd(&g_cnt[tid], s_cnt[tid]);
    __syncthreads();
    for (int j = 0; j < k; ++j) {
        int slot = s_base[le[j]] + ls[j];
        if (slot < ECAP) { g_tok[le[j] * ECAP + slot] = n; g_wgt[le[j] * ECAP + slot] = lv[j]; }
    }
}

// transpose + fp16 convert: W [e][R][C] (C contig) -> T [e][C][R]
__global__ void k_tsplit(const float* __restrict__ W, int which, int R, int C) {
    __shared__ float tile[32][33];
    int e = blockIdx.z, c0 = blockIdx.x * 32, r0 = blockIdx.y * 32;
    const float* We = W + (size_t)e * R * C;
    int tx = threadIdx.x, ty = threadIdx.y;
    for (int i = ty; i < 32; i += 8)
        tile[i][tx] = We[(size_t)(r0 + i) * C + c0 + tx];
    __syncthreads();
    __half* Th = (which ? g_w2h : g_w1h) + (size_t)e * R * C;
    int tid = ty * 32 + tx;
    #pragma unroll
    for (int w = tid; w < 512; w += 256) {
        int c = w >> 4, rp = (w & 15) * 2;
        size_t o = (size_t)(c0 + c) * R + r0 + rp;
        *(__half2*)(Th + o) = __floats2half2_rn(tile[rp][c], tile[rp + 1][c]);
    }
}

__global__ void k_init_out(float* out, int n4) {
    int stride = gridDim.x * blockDim.x;
    float4 z = make_float4(0.f, 0.f, 0.f, 0.f);
    for (int i = blockIdx.x * blockDim.x + threadIdx.x; i < n4; i += stride)
        ((float4*)out)[i] = z;
}

// ---------------- BK=64 chunk compute ----------------
// warp tile 32x64; A fragments via direct per-lane LDG.32, B via ldmatrix from smem
struct AP { const char *p0, *p1, *p2, *p3; };   // row ptrs (g, g+8, g+16, g+24) + lane col offset

__device__ __forceinline__ void chunk_compute(
    AP ap, int kbyte, uint32_t stgB,
    uint32_t bb0, uint32_t bb1, uint32_t bb2, uint32_t bb3,
    uint32_t bxor, uint32_t bcsel, float acc[2][8][4])
{
    #pragma unroll
    for (int ks = 0; ks < 4; ++ks) {
        int kb = kbyte + ks * 32;
        uint32_t a0[4], a1[4], bh[4][4];
        // A fragments (mi=0: rows g,g+8; mi=1: rows g+16,g+24)
        a0[0] = *(const uint32_t*)(ap.p0 + kb);
        a0[1] = *(const uint32_t*)(ap.p1 + kb);
        a0[2] = *(const uint32_t*)(ap.p0 + kb + 16);
        a0[3] = *(const uint32_t*)(ap.p1 + kb + 16);
        a1[0] = *(const uint32_t*)(ap.p2 + kb);
        a1[1] = *(const uint32_t*)(ap.p3 + kb);
        a1[2] = *(const uint32_t*)(ap.p2 + kb + 16);
        a1[3] = *(const uint32_t*)(ap.p3 + kb + 16);
        // B fragments
        uint32_t t = ((uint32_t)(ks * 32) + bcsel) ^ bxor;
        ldsm4(bh[0], stgB + bb0 + t);
        ldsm4(bh[1], stgB + bb1 + t);
        ldsm4(bh[2], stgB + bb2 + t);
        ldsm4(bh[3], stgB + bb3 + t);
        #pragma unroll
        for (int np = 0; np < 4; ++np) {
            mma_f16(acc[0][np * 2],     a0, &bh[np][0]);
            mma_f16(acc[0][np * 2 + 1], a0, &bh[np][2]);
            mma_f16(acc[1][np * 2],     a1, &bh[np][0]);
            mma_f16(acc[1][np * 2 + 1], a1, &bh[np][2]);
        }
    }
}

// ---------------- GEMM1: H = gelu(Xg @ W1 + b1) -> fp16 ----------------
__global__ __launch_bounds__(256, 2) void k_gemm1(const float* __restrict__ b1) {
    int e = blockIdx.z, mt = blockIdx.y, nt = blockIdx.x;
    int cnt = g_cnt[e];
    if (cnt > ECAP) cnt = ECAP;
    if (mt * 128 >= cnt) return;
    int vrows = cnt - mt * 128;
    if (vrows > 128) vrows = 128;

    uint32_t sb = smem_u32(smc);
    int tid = threadIdx.x, wid = tid >> 5, lane = tid & 31;
    int wm = wid & 3, wn = wid >> 2;
    int* s_tok = (int*)smc;
    if (tid < 128) {
        int gi = mt * 128 + tid;
        s_tok[tid] = (gi < cnt) ? g_tok[e * ECAP + gi] : -1;
    }
    __syncthreads();

    // A row pointers (direct gmem fragments)
    int g = lane >> 2, cb = (lane & 3) * 4;
    int r0 = wm * 32 + g;
    int t0 = s_tok[r0],      t1 = s_tok[r0 + 8];
    int t2 = s_tok[r0 + 16], t3 = s_tok[r0 + 24];
    AP ap;
    ap.p0 = (const char*)(g_xh + (size_t)(t0 < 0 ? 0 : t0) * DIMD) + cb;
    ap.p1 = (const char*)(g_xh + (size_t)(t1 < 0 ? 0 : t1) * DIMD) + cb;
    ap.p2 = (const char*)(g_xh + (size_t)(t2 < 0 ? 0 : t2) * DIMD) + cb;
    ap.p3 = (const char*)(g_xh + (size_t)(t3 < 0 ? 0 : t3) * DIMD) + cb;

    // B ldsm address bases
    int brow = ((lane >> 4) << 3) + (lane & 7);
    uint32_t bcsel = (uint32_t)(((lane >> 3) & 1) << 4);
    uint32_t bxor  = (uint32_t)((brow & 7) * 16);
    uint32_t bb0 = (uint32_t)((wn * 64 +  0 + brow) * 128);
    uint32_t bb1 = (uint32_t)((wn * 64 + 16 + brow) * 128);
    uint32_t bb2 = (uint32_t)((wn * 64 + 32 + brow) * 128);
    uint32_t bb3 = (uint32_t)((wn * 64 + 48 + brow) * 128);

    float acc[2][8][4];
    #pragma unroll
    for (int i = 0; i < 2; ++i)
        #pragma unroll
        for (int j = 0; j < 8; ++j)
            #pragma unroll
            for (int q = 0; q < 4; ++q) acc[i][j][q] = 0.0f;

    auto issue = [&](int buf, int kc2) {
        uint32_t stg = sb + SM_STAGE + buf * STG;
        int k0 = kc2 * 64;
        #pragma unroll
        for (int it = 0; it < 4; ++it) {
            int ch = tid + it * 256;
            int row = ch >> 3, c = ch & 7;
            uint32_t dst = stg + (uint32_t)(row * 128) + (uint32_t)((c * 16) ^ ((row & 7) * 16));
            const __half* src = g_w1h + ((size_t)e * HIDH + nt * 128 + row) * DIMD + k0 + c * 8;
            cpa16(dst, src, 16u);
        }
        cp_commit();
    };

    const int KC = DIMD / 64;  // 8
    issue(0, 0); issue(1, 1); issue(2, 2);
    for (int kc = 0; kc < KC; ++kc) {
        if (kc + 3 < KC)       { issue((kc + 3) % 5, kc + 3); cp_wait<3>(); }
        else if (kc + 3 == KC) { cp_wait<2>(); }
        else if (kc + 2 == KC) { cp_wait<1>(); }
        else                   { cp_wait<0>(); }
        __syncthreads();
        int nb = (kc + 1) * 128;                     // prefetch next chunk's A lines
        pf_l1(ap.p0 + nb); pf_l1(ap.p1 + nb); pf_l1(ap.p2 + nb); pf_l1(ap.p3 + nb);
        chunk_compute(ap, kc * 128, sb + SM_STAGE + (kc % 5) * STG,
                      bb0, bb1, bb2, bb3, bxor, bcsel, acc);
        // no trailing sync: writer stage (kc+3)%5 != laggard reader (kc-1)%5
    }

    // epilogue: +bias, exact GELU, store fp16 hidden (private expert region)
    int r_lo = lane >> 2, cbx = (lane & 3) * 2;
    size_t slot0 = (size_t)e * ECAP + mt * 128;
    const float* b1e = b1 + (size_t)e * HIDH;
    #pragma unroll
    for (int mi = 0; mi < 2; ++mi)
        #pragma unroll
        for (int hh = 0; hh < 2; ++hh) {
            int row = wm * 32 + mi * 16 + hh * 8 + r_lo;
            if (row >= vrows) continue;
            size_t sbase = (slot0 + row) * HIDH;
            #pragma unroll
            for (int ni = 0; ni < 8; ++ni) {
                int col = nt * 128 + wn * 64 + ni * 8 + cbx;
                float v0 = acc[mi][ni][hh * 2 + 0] + b1e[col];
                float v1 = acc[mi][ni][hh * 2 + 1] + b1e[col + 1];
                float q0 = 0.5f * v0 * (1.0f + erff(v0 * 0.70710678118654752f));
                float q1 = 0.5f * v1 * (1.0f + erff(v1 * 0.70710678118654752f));
                *(__half2*)(g_hh + sbase + col) = __floats2half2_rn(q0, q1);
            }
        }
}

// ---------------- GEMM2: Y = H @ W2 + b2; out[tok] += w * Y ----------------
__global__ __launch_bounds__(256, 2) void k_gemm2(const float* __restrict__ b2,
                                                  float* __restrict__ out) {
    int e = blockIdx.z, mt = blockIdx.y, nt = blockIdx.x;
    int cnt = g_cnt[e];
    if (cnt > ECAP) cnt = ECAP;
    if (mt * 128 >= cnt) return;

    uint32_t sb = smem_u32(smc);
    int tid = threadIdx.x, wid = tid >> 5, lane = tid & 31;
    int wm = wid & 3, wn = wid >> 2;
    int* s_tok = (int*)smc;
    float* s_wgt = (float*)(smc + 512);
    if (tid < 128) {
        int gi = mt * 128 + tid;
        bool ok = gi < cnt;
        s_tok[tid] = ok ? g_tok[e * ECAP + gi] : -1;
        s_wgt[tid] = ok ? g_wgt[e * ECAP + gi] : 0.0f;
    }
    __syncthreads();

    // A row pointers: contiguous hidden slots (rows >= cnt read finite garbage; masked later)
    int g = lane >> 2, cb = (lane & 3) * 4;
    size_t ar = (size_t)e * ECAP + mt * 128 + wm * 32 + g;
    AP ap;
    ap.p0 = (const char*)(g_hh + ar * HIDH) + cb;
    ap.p1 = (const char*)(g_hh + (ar + 8) * HIDH) + cb;
    ap.p2 = (const char*)(g_hh + (ar + 16) * HIDH) + cb;
    ap.p3 = (const char*)(g_hh + (ar + 24) * HIDH) + cb;

    int brow = ((lane >> 4) << 3) + (lane & 7);
    uint32_t bcsel = (uint32_t)(((lane >> 3) & 1) << 4);
    uint32_t bxor  = (uint32_t)((brow & 7) * 16);
    uint32_t bb0 = (uint32_t)((wn * 64 +  0 + brow) * 128);
    uint32_t bb1 = (uint32_t)((wn * 64 + 16 + brow) * 128);
    uint32_t bb2 = (uint32_t)((wn * 64 + 32 + brow) * 128);
    uint32_t bb3 = (uint32_t)((wn * 64 + 48 + brow) * 128);

    float acc[2][8][4];
    #pragma unroll
    for (int i = 0; i < 2; ++i)
        #pragma unroll
        for (int j = 0; j < 8; ++j)
            #pragma unroll
            for (int q = 0; q < 4; ++q) acc[i][j][q] = 0.0f;

    auto issue = [&](int buf, int kc2) {
        uint32_t stg = sb + SM_STAGE + buf * STG;
        int k0 = kc2 * 64;
        #pragma unroll
        for (int it = 0; it < 4; ++it) {
            int ch = tid + it * 256;
            int row = ch >> 3, c = ch & 7;
            uint32_t dst = stg + (uint32_t)(row * 128) + (uint32_t)((c * 16) ^ ((row & 7) * 16));
            const __half* src = g_w2h + ((size_t)e * DIMD + nt * 128 + row) * HIDH + k0 + c * 8;
            cpa16(dst, src, 16u);
        }
        cp_commit();
    };

    const int KC = HIDH / 64;  // 16
    issue(0, 0); issue(1, 1); issue(2, 2);
    for (int kc = 0; kc < KC; ++kc) {
        if (kc + 3 < KC)       { issue((kc + 3) % 5, kc + 3); cp_wait<3>(); }
        else if (kc + 3 == KC) { cp_wait<2>(); }
        else if (kc + 2 == KC) { cp_wait<1>(); }
        else                   { cp_wait<0>(); }
        __syncthreads();
        int nb = (kc + 1) * 128;
        pf_l1(ap.p0 + nb); pf_l1(ap.p1 + nb); pf_l1(ap.p2 + nb); pf_l1(ap.p3 + nb);
        chunk_compute(ap, kc * 128, sb + SM_STAGE + (kc % 5) * STG,
                      bb0, bb1, bb2, bb3, bxor, bcsel, acc);
    }

    // epilogue: +b2, weighted scatter-add into out
    int r_lo = lane >> 2, cbx = (lane & 3) * 2;
    const float* b2e = b2 + (size_t)e * DIMD;
    #pragma unroll
    for (int mi = 0; mi < 2; ++mi)
        #pragma unroll
        for (int hh = 0; hh < 2; ++hh) {
            int row = wm * 32 + mi * 16 + hh * 8 + r_lo;
            int tok = s_tok[row];
            float w = s_wgt[row];
            if (tok < 0 || w == 0.0f) continue;
            float* orow = out + (size_t)tok * DIMD;
            #pragma unroll
            for (int ni = 0; ni < 8; ++ni) {
                int col = nt * 128 + wn * 64 + ni * 8 + cbx;
                float y0 = acc[mi][ni][hh * 2 + 0] + b2e[col];
                float y1 = acc[mi][ni][hh * 2 + 1] + b2e[col + 1];
                atomicAdd(orow + col,     w * y0);
                atomicAdd(orow + col + 1, w * y1);
            }
        }
}

// ---------------- launch ----------------
extern "C" void kernel_launch(void* const* d_in, const int* in_sizes, int n_in,
                              void* d_out, int out_size) {
    const float* x  = (const float*)d_in[0];
    const float* rt = (const float*)d_in[1];
    const float* W1 = (const float*)d_in[2];
    const float* b1 = (const float*)d_in[3];
    const float* W2 = (const float*)d_in[4];
    const float* b2 = (const float*)d_in[5];
    float* out = (float*)d_out;

    cudaFuncSetAttribute(k_gemm1, cudaFuncAttributeMaxDynamicSharedMemorySize, SMEM_DYN);
    cudaFuncSetAttribute(k_gemm2, cudaFuncAttributeMaxDynamicSharedMemorySize, SMEM_DYN);

    dim3 tb(32, 8);
    // order chosen so k_gemm1 is the 4th launch (ncu -s window)
    k_split_x<<<(TOKS * DIMD / 4 + 255) / 256, 256>>>(x);       // also zeros g_cnt
    k_scatter<<<TOKS / 256, 256>>>(rt);
    k_tsplit<<<dim3(HIDH / 32, DIMD / 32, NEXP), tb>>>(W1, 0, DIMD, HIDH);
    k_gemm1<<<dim3(HIDH / 128, ECAP / 128, NEXP), 256, SMEM_DYN>>>(b1);
    k_tsplit<<<dim3(DIMD / 32, HIDH / 32, NEXP), tb>>>(W2, 1, HIDH, DIMD);
    k_init_out<<<256, 256>>>(out, out_size / 4);
    k_gemm2<<<dim3(DIMD / 128, ECAP / 128, NEXP), 256, SMEM_DYN>>>(b2, out);
}

// round 12
// speedup vs baseline: 1.5296x; 1.5296x over previous
#include <cuda_runtime.h>
#include <cuda_fp16.h>
#include <stdint.h>

#define TOKS 8192
#define DIMD 512
#define HIDH 1024
#define NEXP 16
#define ECAP 2048                    // fixed capacity per expert (mean 1024, >30 sigma)
#define HROWS (NEXP * ECAP)

// ---------------- device scratch ----------------
__device__ int   g_cnt[NEXP];
__device__ int   g_tok[NEXP * ECAP];
__device__ float g_wgt[NEXP * ECAP];
__device__ __align__(256) __half g_xh[TOKS * DIMD];                  // x (fp16)
__device__ __align__(256) __half g_w1h[NEXP * HIDH * DIMD];          // W1^T: [e][h][d] fp16
__device__ __align__(256) __half g_w2h[NEXP * DIMD * HIDH];          // W2^T: [e][dout][h] fp16
__device__ __align__(256) __half g_hh[(size_t)HROWS * HIDH];         // gelu hidden (fp16)

// ---------------- helpers ----------------
__device__ __forceinline__ uint32_t smem_u32(const void* p) {
    uint32_t a;
    asm("{ .reg .u64 t; cvta.to.shared.u64 t, %1; cvt.u32.u64 %0, t; }" : "=r"(a) : "l"(p));
    return a;
}
__device__ __forceinline__ void cpa16(uint32_t dst, const void* src, uint32_t sz) {
    asm volatile("cp.async.cg.shared.global [%0], [%1], 16, %2;"
                 :: "r"(dst), "l"(src), "r"(sz) : "memory");
}
__device__ __forceinline__ void cp_commit() {
    asm volatile("cp.async.commit_group;" ::: "memory");
}
template <int N>
__device__ __forceinline__ void cp_wait() {
    asm volatile("cp.async.wait_group %0;" :: "n"(N) : "memory");
}
__device__ __forceinline__ void ldsm4(uint32_t* r, uint32_t addr) {
    asm volatile("ldmatrix.sync.aligned.m8n8.x4.shared.b16 {%0,%1,%2,%3}, [%4];"
                 : "=r"(r[0]), "=r"(r[1]), "=r"(r[2]), "=r"(r[3]) : "r"(addr));
}
__device__ __forceinline__ void mma_f16(float* d, const uint32_t* a, const uint32_t* b) {
    asm volatile(
        "mma.sync.aligned.m16n8k16.row.col.f32.f16.f16.f32 "
        "{%0,%1,%2,%3}, {%4,%5,%6,%7}, {%8,%9}, {%0,%1,%2,%3};"
        : "+f"(d[0]), "+f"(d[1]), "+f"(d[2]), "+f"(d[3])
        : "r"(a[0]), "r"(a[1]), "r"(a[2]), "r"(a[3]), "r"(b[0]), "r"(b[1]));
}

// smem: s_tok[128] @0, s_wgt[128] @512, 3 stages @1024
// stage (BK=64): A [128 x 128B SW128] @0 ; B [128 x 128B SW128] @16384
// addr = row*128 + ((t) ^ ((row&7)*16))
#define OFF_B    16384
#define STG      32768
#define SM_STAGE 1024
#define SMEM_DYN (SM_STAGE + 3 * STG)   // 99328 (x2 CTAs = 198656 <= 228KB/SM)

extern __shared__ __align__(1024) char smc[];

// ---------------- prep kernels ----------------
// also zeroes `out` (same float4 index space: TOKS*DIMD) and g_cnt
__global__ void k_split_x(const float* __restrict__ x, float* __restrict__ out) {
    if (blockIdx.x == 0 && threadIdx.x < NEXP) g_cnt[threadIdx.x] = 0;
    int i = blockIdx.x * 256 + threadIdx.x;
    if (i < TOKS * DIMD / 4) {
        float4 v = ((const float4*)x)[i];
        ((__half2*)g_xh)[i * 2]     = __floats2half2_rn(v.x, v.y);
        ((__half2*)g_xh)[i * 2 + 1] = __floats2half2_rn(v.z, v.w);
        ((float4*)out)[i] = make_float4(0.f, 0.f, 0.f, 0.f);
    }
}

__global__ void k_scatter(const float* __restrict__ rt) {
    __shared__ int s_cnt[NEXP], s_base[NEXP];
    int tid = threadIdx.x;
    int n = blockIdx.x * 256 + tid;
    if (tid < NEXP) s_cnt[tid] = 0;
    __syncthreads();
    float v[NEXP];
    const float4* r4 = (const float4*)(rt + (size_t)n * NEXP);
    float4 a = r4[0], b = r4[1], c = r4[2], d = r4[3];
    v[0]=a.x; v[1]=a.y; v[2]=a.z; v[3]=a.w; v[4]=b.x; v[5]=b.y; v[6]=b.z; v[7]=b.w;
    v[8]=c.x; v[9]=c.y; v[10]=c.z; v[11]=c.w; v[12]=d.x; v[13]=d.y; v[14]=d.z; v[15]=d.w;
    int le[4]; float lv[4]; int ls[4]; int k = 0;
    #pragma unroll
    for (int e = 0; e < NEXP; ++e)
        if (v[e] > 0.0f && k < 4) { le[k] = e; lv[k] = v[e]; ls[k] = atomicAdd(&s_cnt[e], 1); ++k; }
    __syncthreads();
    if (tid < NEXP) s_base[tid] = atomicAdd(&g_cnt[tid], s_cnt[tid]);
    __syncthreads();
    for (int j = 0; j < k; ++j) {
        int slot = s_base[le[j]] + ls[j];
        if (slot < ECAP) { g_tok[le[j] * ECAP + slot] = n; g_wgt[le[j] * ECAP + slot] = lv[j]; }
    }
}

// transpose + fp16 convert: W [e][R][C] (C contig) -> T [e][C][R]
__global__ void k_tsplit(const float* __restrict__ W, int which, int R, int C) {
    __shared__ float tile[32][33];
    int e = blockIdx.z, c0 = blockIdx.x * 32, r0 = blockIdx.y * 32;
    const float* We = W + (size_t)e * R * C;
    int tx = threadIdx.x, ty = threadIdx.y;
    for (int i = ty; i < 32; i += 8)
        tile[i][tx] = We[(size_t)(r0 + i) * C + c0 + tx];
    __syncthreads();
    __half* Th = (which ? g_w2h : g_w1h) + (size_t)e * R * C;
    int tid = ty * 32 + tx;
    #pragma unroll
    for (int w = tid; w < 512; w += 256) {
        int c = w >> 4, rp = (w & 15) * 2;
        size_t o = (size_t)(c0 + c) * R + r0 + rp;
        *(__half2*)(Th + o) = __floats2half2_rn(tile[rp][c], tile[rp + 1][c]);
    }
}

// ---------------- BK=64 chunk compute ----------------
// CTA 128x128, 8 warps: wm = wid&3 (32 rows), wn = wid>>2 (64 cols)
// A and B both in smem, SW128 layout; 4 k16 steps per chunk.
__device__ __forceinline__ void chunk64(
    uint32_t stg,
    uint32_t ab0, uint32_t ab1, uint32_t axor, uint32_t acsel,
    uint32_t bb0, uint32_t bb1, uint32_t bb2, uint32_t bb3,
    uint32_t bxor, uint32_t bcsel, float acc[2][8][4])
{
    #pragma unroll
    for (int ks = 0; ks < 4; ++ks) {
        uint32_t ta = ((uint32_t)(ks * 32) + acsel) ^ axor;
        uint32_t tb = ((uint32_t)(ks * 32) + bcsel) ^ bxor;
        uint32_t a0[4], a1[4], bh[4][4];
        ldsm4(a0, stg + ab0 + ta);
        ldsm4(a1, stg + ab1 + ta);
        ldsm4(bh[0], stg + OFF_B + bb0 + tb);
        ldsm4(bh[1], stg + OFF_B + bb1 + tb);
        ldsm4(bh[2], stg + OFF_B + bb2 + tb);
        ldsm4(bh[3], stg + OFF_B + bb3 + tb);
        #pragma unroll
        for (int np = 0; np < 4; ++np) {
            mma_f16(acc[0][np * 2],     a0, &bh[np][0]);
            mma_f16(acc[0][np * 2 + 1], a0, &bh[np][2]);
            mma_f16(acc[1][np * 2],     a1, &bh[np][0]);
            mma_f16(acc[1][np * 2 + 1], a1, &bh[np][2]);
        }
    }
}

// ---------------- GEMM1: H = gelu(Xg @ W1 + b1) -> fp16 ----------------
__global__ __launch_bounds__(256, 2) void k_gemm1(const float* __restrict__ b1) {
    int e = blockIdx.z, mt = blockIdx.y, nt = blockIdx.x;
    int cnt = g_cnt[e];
    if (cnt > ECAP) cnt = ECAP;
    if (mt * 128 >= cnt) return;
    int vrows = cnt - mt * 128;
    if (vrows > 128) vrows = 128;

    uint32_t sb = smem_u32(smc);
    int tid = threadIdx.x, wid = tid >> 5, lane = tid & 31;
    int wm = wid & 3, wn = wid >> 2;
    int* s_tok = (int*)smc;
    if (tid < 128) {
        int gi = mt * 128 + tid;
        s_tok[tid] = (gi < cnt) ? g_tok[e * ECAP + gi] : -1;
    }
    __syncthreads();

    // A ldsm address components
    int arow = lane & 15;
    uint32_t acsel = (uint32_t)((lane >> 4) << 4);
    uint32_t axor  = (uint32_t)((arow & 7) * 16);
    uint32_t ab0 = (uint32_t)((wm * 32 + arow) * 128);
    uint32_t ab1 = (uint32_t)((wm * 32 + 16 + arow) * 128);
    // B ldsm address components
    int brow = ((lane >> 4) << 3) + (lane & 7);
    uint32_t bcsel = (uint32_t)(((lane >> 3) & 1) << 4);
    uint32_t bxor  = (uint32_t)((brow & 7) * 16);
    uint32_t bb0 = (uint32_t)((wn * 64 +  0 + brow) * 128);
    uint32_t bb1 = (uint32_t)((wn * 64 + 16 + brow) * 128);
    uint32_t bb2 = (uint32_t)((wn * 64 + 32 + brow) * 128);
    uint32_t bb3 = (uint32_t)((wn * 64 + 48 + brow) * 128);

    float acc[2][8][4];
    #pragma unroll
    for (int i = 0; i < 2; ++i)
        #pragma unroll
        for (int j = 0; j < 8; ++j)
            #pragma unroll
            for (int q = 0; q < 4; ++q) acc[i][j][q] = 0.0f;

    auto issue = [&](int buf, int kc2) {
        uint32_t stg = sb + SM_STAGE + buf * STG;
        int k0 = kc2 * 64;
        #pragma unroll
        for (int it = 0; it < 4; ++it) {      // A: 1024 chunks of 16B (gather)
            int ch = tid + it * 256;
            int row = ch >> 3, c = ch & 7;
            uint32_t dst = stg + (uint32_t)(row * 128) + (uint32_t)((c * 16) ^ ((row & 7) * 16));
            int tok = s_tok[row];
            uint32_t sz = (tok < 0) ? 0u : 16u;
            const __half* src = g_xh + (size_t)(tok < 0 ? 0 : tok) * DIMD + k0 + c * 8;
            cpa16(dst, src, sz);
        }
        #pragma unroll
        for (int it = 0; it < 4; ++it) {      // B: 1024 chunks of 16B
            int ch = tid + it * 256;
            int row = ch >> 3, c = ch & 7;
            uint32_t dst = stg + OFF_B + (uint32_t)(row * 128) + (uint32_t)((c * 16) ^ ((row & 7) * 16));
            const __half* src = g_w1h + ((size_t)e * HIDH + nt * 128 + row) * DIMD + k0 + c * 8;
            cpa16(dst, src, 16u);
        }
        cp_commit();
    };

    const int KC = DIMD / 64;  // 8
    issue(0, 0); issue(1, 1);
    for (int kc = 0; kc < KC; ++kc) {
        if (kc + 2 < KC)       { issue((kc + 2) % 3, kc + 2); cp_wait<2>(); }
        else if (kc + 2 == KC) { cp_wait<1>(); }
        else                   { cp_wait<0>(); }
        __syncthreads();
        chunk64(sb + SM_STAGE + (kc % 3) * STG,
                ab0, ab1, axor, acsel, bb0, bb1, bb2, bb3, bxor, bcsel, acc);
        __syncthreads();
    }

    // epilogue: +bias, exact GELU, store fp16 hidden (private expert region)
    int r_lo = lane >> 2, cbx = (lane & 3) * 2;
    size_t slot0 = (size_t)e * ECAP + mt * 128;
    const float* b1e = b1 + (size_t)e * HIDH;
    #pragma unroll
    for (int mi = 0; mi < 2; ++mi)
        #pragma unroll
        for (int hh = 0; hh < 2; ++hh) {
            int row = wm * 32 + mi * 16 + hh * 8 + r_lo;
            if (row >= vrows) continue;
            size_t sbase = (slot0 + row) * HIDH;
            #pragma unroll
            for (int ni = 0; ni < 8; ++ni) {
                int col = nt * 128 + wn * 64 + ni * 8 + cbx;
                float v0 = acc[mi][ni][hh * 2 + 0] + b1e[col];
                float v1 = acc[mi][ni][hh * 2 + 1] + b1e[col + 1];
                float q0 = 0.5f * v0 * (1.0f + erff(v0 * 0.70710678118654752f));
                float q1 = 0.5f * v1 * (1.0f + erff(v1 * 0.70710678118654752f));
                *(__half2*)(g_hh + sbase + col) = __floats2half2_rn(q0, q1);
            }
        }
}

// ---------------- GEMM2: Y = H @ W2 + b2; out[tok] += w * Y ----------------
__global__ __launch_bounds__(256, 2) void k_gemm2(const float* __restrict__ b2,
                                                  float* __restrict__ out) {
    int e = blockIdx.z, mt = blockIdx.y, nt = blockIdx.x;
    int cnt = g_cnt[e];
    if (cnt > ECAP) cnt = ECAP;
    if (mt * 128 >= cnt) return;

    uint32_t sb = smem_u32(smc);
    int tid = threadIdx.x, wid = tid >> 5, lane = tid & 31;
    int wm = wid & 3, wn = wid >> 2;
    int* s_tok = (int*)smc;
    float* s_wgt = (float*)(smc + 512);
    if (tid < 128) {
        int gi = mt * 128 + tid;
        bool ok = gi < cnt;
        s_tok[tid] = ok ? g_tok[e * ECAP + gi] : -1;
        s_wgt[tid] = ok ? g_wgt[e * ECAP + gi] : 0.0f;
    }
    __syncthreads();

    int arow = lane & 15;
    uint32_t acsel = (uint32_t)((lane >> 4) << 4);
    uint32_t axor  = (uint32_t)((arow & 7) * 16);
    uint32_t ab0 = (uint32_t)((wm * 32 + arow) * 128);
    uint32_t ab1 = (uint32_t)((wm * 32 + 16 + arow) * 128);
    int brow = ((lane >> 4) << 3) + (lane & 7);
    uint32_t bcsel = (uint32_t)(((lane >> 3) & 1) << 4);
    uint32_t bxor  = (uint32_t)((brow & 7) * 16);
    uint32_t bb0 = (uint32_t)((wn * 64 +  0 + brow) * 128);
    uint32_t bb1 = (uint32_t)((wn * 64 + 16 + brow) * 128);
    uint32_t bb2 = (uint32_t)((wn * 64 + 32 + brow) * 128);
    uint32_t bb3 = (uint32_t)((wn * 64 + 48 + brow) * 128);

    float acc[2][8][4];
    #pragma unroll
    for (int i = 0; i < 2; ++i)
        #pragma unroll
        for (int j = 0; j < 8; ++j)
            #pragma unroll
            for (int q = 0; q < 4; ++q) acc[i][j][q] = 0.0f;

    auto issue = [&](int buf, int kc2) {
        uint32_t stg = sb + SM_STAGE + buf * STG;
        int k0 = kc2 * 64;
        #pragma unroll
        for (int it = 0; it < 4; ++it) {      // A: hidden fp16 rows (contiguous slots)
            int ch = tid + it * 256;
            int row = ch >> 3, c = ch & 7;
            uint32_t dst = stg + (uint32_t)(row * 128) + (uint32_t)((c * 16) ^ ((row & 7) * 16));
            const __half* src = g_hh + ((size_t)e * ECAP + mt * 128 + row) * HIDH + k0 + c * 8;
            cpa16(dst, src, 16u);
        }
        #pragma unroll
        for (int it = 0; it < 4; ++it) {      // B: W2^T rows
            int ch = tid + it * 256;
            int row = ch >> 3, c = ch & 7;
            uint32_t dst = stg + OFF_B + (uint32_t)(row * 128) + (uint32_t)((c * 16) ^ ((row & 7) * 16));
            const __half* src = g_w2h + ((size_t)e * DIMD + nt * 128 + row) * HIDH + k0 + c * 8;
            cpa16(dst, src, 16u);
        }
        cp_commit();
    };

    const int KC = HIDH / 64;  // 16
    issue(0, 0); issue(1, 1);
    for (int kc = 0; kc < KC; ++kc) {
        if (kc + 2 < KC)       { issue((kc + 2) % 3, kc + 2); cp_wait<2>(); }
        else if (kc + 2 == KC) { cp_wait<1>(); }
        else                   { cp_wait<0>(); }
        __syncthreads();
        chunk64(sb + SM_STAGE + (kc % 3) * STG,
                ab0, ab1, axor, acsel, bb0, bb1, bb2, bb3, bxor, bcsel, acc);
        __syncthreads();
    }

    // epilogue: +b2, weighted scatter-add into out
    int r_lo = lane >> 2, cbx = (lane & 3) * 2;
    const float* b2e = b2 + (size_t)e * DIMD;
    #pragma unroll
    for (int mi = 0; mi < 2; ++mi)
        #pragma unroll
        for (int hh = 0; hh < 2; ++hh) {
            int row = wm * 32 + mi * 16 + hh * 8 + r_lo;
            int tok = s_tok[row];
            float w = s_wgt[row];
            if (tok < 0 || w == 0.0f) continue;
            float* orow = out + (size_t)tok * DIMD;
            #pragma unroll
            for (int ni = 0; ni < 8; ++ni) {
                int col = nt * 128 + wn * 64 + ni * 8 + cbx;
                float y0 = acc[mi][ni][hh * 2 + 0] + b2e[col];
                float y1 = acc[mi][ni][hh * 2 + 1] + b2e[col + 1];
                atomicAdd(orow + col,     w * y0);
                atomicAdd(orow + col + 1, w * y1);
            }
        }
}

// ---------------- launch ----------------
extern "C" void kernel_launch(void* const* d_in, const int* in_sizes, int n_in,
                              void* d_out, int out_size) {
    const float* x  = (const float*)d_in[0];
    const float* rt = (const float*)d_in[1];
    const float* W1 = (const float*)d_in[2];
    const float* b1 = (const float*)d_in[3];
    const float* W2 = (const float*)d_in[4];
    const float* b2 = (const float*)d_in[5];
    float* out = (float*)d_out;

    cudaFuncSetAttribute(k_gemm1, cudaFuncAttributeMaxDynamicSharedMemorySize, SMEM_DYN);
    cudaFuncSetAttribute(k_gemm2, cudaFuncAttributeMaxDynamicSharedMemorySize, SMEM_DYN);

    dim3 tb(32, 8);
    // order chosen so k_gemm1 is the 4th launch (ncu -s window)
    k_split_x<<<(TOKS * DIMD / 4 + 255) / 256, 256>>>(x, out);  // also zeros out + g_cnt
    k_scatter<<<TOKS / 256, 256>>>(rt);
    k_tsplit<<<dim3(HIDH / 32, DIMD / 32, NEXP), tb>>>(W1, 0, DIMD, HIDH);
    k_gemm1<<<dim3(HIDH / 128, ECAP / 128, NEXP), 256, SMEM_DYN>>>(b1);
    k_tsplit<<<dim3(DIMD / 32, HIDH / 32, NEXP), tb>>>(W2, 1, HIDH, DIMD);
    k_gemm2<<<dim3(DIMD / 128, ECAP / 128, NEXP), 256, SMEM_DYN>>>(b2, out);
}

// round 13
// speedup vs baseline: 1.5437x; 1.0092x over previous
#include <cuda_runtime.h>
#include <cuda_fp16.h>
#include <stdint.h>

#define TOKS 8192
#define DIMD 512
#define HIDH 1024
#define NEXP 16
#define ECAP 2048                    // fixed capacity per expert (mean 1024, >30 sigma)
#define HROWS (NEXP * ECAP)

// ---------------- device scratch ----------------
__device__ int   g_cnt[NEXP];
__device__ int   g_tok[NEXP * ECAP];
__device__ float g_wgt[NEXP * ECAP];
__device__ __align__(256) __half g_xh[TOKS * DIMD];                  // x (fp16)
__device__ __align__(256) __half g_w1h[NEXP * HIDH * DIMD];          // W1^T: [e][h][d] fp16
__device__ __align__(256) __half g_w2h[NEXP * DIMD * HIDH];          // W2^T: [e][dout][h] fp16
__device__ __align__(256) __half g_hh[(size_t)HROWS * HIDH];         // gelu hidden (fp16)

// ---------------- helpers ----------------
__device__ __forceinline__ uint32_t smem_u32(const void* p) {
    uint32_t a;
    asm("{ .reg .u64 t; cvta.to.shared.u64 t, %1; cvt.u32.u64 %0, t; }" : "=r"(a) : "l"(p));
    return a;
}
__device__ __forceinline__ void cpa16(uint32_t dst, const void* src, uint32_t sz) {
    asm volatile("cp.async.cg.shared.global [%0], [%1], 16, %2;"
                 :: "r"(dst), "l"(src), "r"(sz) : "memory");
}
__device__ __forceinline__ void cp_commit() {
    asm volatile("cp.async.commit_group;" ::: "memory");
}
template <int N>
__device__ __forceinline__ void cp_wait() {
    asm volatile("cp.async.wait_group %0;" :: "n"(N) : "memory");
}
__device__ __forceinline__ void ldsm4(uint32_t* r, uint32_t addr) {
    asm volatile("ldmatrix.sync.aligned.m8n8.x4.shared.b16 {%0,%1,%2,%3}, [%4];"
                 : "=r"(r[0]), "=r"(r[1]), "=r"(r[2]), "=r"(r[3]) : "r"(addr));
}
__device__ __forceinline__ void mma_f16(float* d, const uint32_t* a, const uint32_t* b) {
    asm volatile(
        "mma.sync.aligned.m16n8k16.row.col.f32.f16.f16.f32 "
        "{%0,%1,%2,%3}, {%4,%5,%6,%7}, {%8,%9}, {%0,%1,%2,%3};"
        : "+f"(d[0]), "+f"(d[1]), "+f"(d[2]), "+f"(d[3])
        : "r"(a[0]), "r"(a[1]), "r"(a[2]), "r"(a[3]), "r"(b[0]), "r"(b[1]));
}

// smem: s_tok[128] @0, s_wgt[128] @512, 3 stages @1024
// stage (BK=64): A [128 x 128B SW128] @0 ; B [128 x 128B SW128] @16384
// addr = row*128 + ((t) ^ ((row&7)*16))
#define OFF_B    16384
#define STG      32768
#define SM_STAGE 1024
#define SMEM_DYN (SM_STAGE + 3 * STG)   // 99328 (x2 CTAs = 198656 <= 228KB/SM)

extern __shared__ __align__(1024) char smc[];

// ---------------- prep kernels ----------------
// also zeroes `out` (same float4 index space: TOKS*DIMD) and g_cnt
__global__ void k_split_x(const float* __restrict__ x, float* __restrict__ out) {
    if (blockIdx.x == 0 && threadIdx.x < NEXP) g_cnt[threadIdx.x] = 0;
    int i = blockIdx.x * 256 + threadIdx.x;
    if (i < TOKS * DIMD / 4) {
        float4 v = ((const float4*)x)[i];
        ((__half2*)g_xh)[i * 2]     = __floats2half2_rn(v.x, v.y);
        ((__half2*)g_xh)[i * 2 + 1] = __floats2half2_rn(v.z, v.w);
        ((float4*)out)[i] = make_float4(0.f, 0.f, 0.f, 0.f);
    }
}

__global__ void k_scatter(const float* __restrict__ rt) {
    __shared__ int s_cnt[NEXP], s_base[NEXP];
    int tid = threadIdx.x;
    int n = blockIdx.x * 256 + tid;
    if (tid < NEXP) s_cnt[tid] = 0;
    __syncthreads();
    float v[NEXP];
    const float4* r4 = (const float4*)(rt + (size_t)n * NEXP);
    float4 a = r4[0], b = r4[1], c = r4[2], d = r4[3];
    v[0]=a.x; v[1]=a.y; v[2]=a.z; v[3]=a.w; v[4]=b.x; v[5]=b.y; v[6]=b.z; v[7]=b.w;
    v[8]=c.x; v[9]=c.y; v[10]=c.z; v[11]=c.w; v[12]=d.x; v[13]=d.y; v[14]=d.z; v[15]=d.w;
    int le[4]; float lv[4]; int ls[4]; int k = 0;
    #pragma unroll
    for (int e = 0; e < NEXP; ++e)
        if (v[e] > 0.0f && k < 4) { le[k] = e; lv[k] = v[e]; ls[k] = atomicAdd(&s_cnt[e], 1); ++k; }
    __syncthreads();
    if (tid < NEXP) s_base[tid] = atomicAdd(&g_cnt[tid], s_cnt[tid]);
    __syncthreads();
    for (int j = 0; j < k; ++j) {
        int slot = s_base[le[j]] + ls[j];
        if (slot < ECAP) { g_tok[le[j] * ECAP + slot] = n; g_wgt[le[j] * ECAP + slot] = lv[j]; }
    }
}

// transpose + fp16 convert: W [e][R][C] (C contig) -> T [e][C][R]
__global__ void k_tsplit(const float* __restrict__ W, int which, int R, int C) {
    __shared__ float tile[32][33];
    int e = blockIdx.z, c0 = blockIdx.x * 32, r0 = blockIdx.y * 32;
    const float* We = W + (size_t)e * R * C;
    int tx = threadIdx.x, ty = threadIdx.y;
    for (int i = ty; i < 32; i += 8)
        tile[i][tx] = We[(size_t)(r0 + i) * C + c0 + tx];
    __syncthreads();
    __half* Th = (which ? g_w2h : g_w1h) + (size_t)e * R * C;
    int tid = ty * 32 + tx;
    #pragma unroll
    for (int w = tid; w < 512; w += 256) {
        int c = w >> 4, rp = (w & 15) * 2;
        size_t o = (size_t)(c0 + c) * R + r0 + rp;
        *(__half2*)(Th + o) = __floats2half2_rn(tile[rp][c], tile[rp + 1][c]);
    }
}

// ---------------- BK=64 chunk compute ----------------
// CTA 128x128, 4 warps (128 thr): wm = wid&1 (64 rows), wn = wid>>1 (64 cols)
// warp tile 64x64: 4 m-tiles x 8 n-tiles; acc[4][8][4]
__device__ __forceinline__ void chunk64(
    uint32_t stg,
    const uint32_t* ab, uint32_t axor, uint32_t acsel,
    const uint32_t* bb, uint32_t bxor, uint32_t bcsel,
    float acc[4][8][4])
{
    #pragma unroll
    for (int ks = 0; ks < 4; ++ks) {
        uint32_t ta = ((uint32_t)(ks * 32) + acsel) ^ axor;
        uint32_t tb = ((uint32_t)(ks * 32) + bcsel) ^ bxor;
        uint32_t a[4][4], bh[4][4];
        #pragma unroll
        for (int mi = 0; mi < 4; ++mi) ldsm4(a[mi], stg + ab[mi] + ta);
        #pragma unroll
        for (int nj = 0; nj < 4; ++nj) ldsm4(bh[nj], stg + OFF_B + bb[nj] + tb);
        #pragma unroll
        for (int mi = 0; mi < 4; ++mi)
            #pragma unroll
            for (int nj = 0; nj < 4; ++nj) {
                mma_f16(acc[mi][nj * 2],     a[mi], &bh[nj][0]);
                mma_f16(acc[mi][nj * 2 + 1], a[mi], &bh[nj][2]);
            }
    }
}

// ---------------- GEMM1: H = gelu(Xg @ W1 + b1) -> fp16 ----------------
__global__ __launch_bounds__(128, 2) void k_gemm1(const float* __restrict__ b1) {
    int e = blockIdx.z, mt = blockIdx.y, nt = blockIdx.x;
    int cnt = g_cnt[e];
    if (cnt > ECAP) cnt = ECAP;
    if (mt * 128 >= cnt) return;
    int vrows = cnt - mt * 128;
    if (vrows > 128) vrows = 128;

    uint32_t sb = smem_u32(smc);
    int tid = threadIdx.x, wid = tid >> 5, lane = tid & 31;
    int wm = wid & 1, wn = wid >> 1;
    int* s_tok = (int*)smc;
    {
        int gi = mt * 128 + tid;
        s_tok[tid] = (gi < cnt) ? g_tok[e * ECAP + gi] : -1;
    }
    __syncthreads();

    // A ldsm address components (4 m-tiles of 16 rows)
    int arow = lane & 15;
    uint32_t acsel = (uint32_t)((lane >> 4) << 4);
    uint32_t axor  = (uint32_t)((arow & 7) * 16);
    uint32_t ab[4];
    #pragma unroll
    for (int mi = 0; mi < 4; ++mi) ab[mi] = (uint32_t)((wm * 64 + mi * 16 + arow) * 128);
    // B ldsm address components (4 ldsm of 16 cols each)
    int brow = ((lane >> 4) << 3) + (lane & 7);
    uint32_t bcsel = (uint32_t)(((lane >> 3) & 1) << 4);
    uint32_t bxor  = (uint32_t)((brow & 7) * 16);
    uint32_t bb[4];
    #pragma unroll
    for (int nj = 0; nj < 4; ++nj) bb[nj] = (uint32_t)((wn * 64 + nj * 16 + brow) * 128);

    float acc[4][8][4];
    #pragma unroll
    for (int i = 0; i < 4; ++i)
        #pragma unroll
        for (int j = 0; j < 8; ++j)
            #pragma unroll
            for (int q = 0; q < 4; ++q) acc[i][j][q] = 0.0f;

    auto issue = [&](int buf, int kc2) {
        uint32_t stg = sb + SM_STAGE + buf * STG;
        int k0 = kc2 * 64;
        #pragma unroll
        for (int it = 0; it < 8; ++it) {      // A: 1024 chunks of 16B (gather)
            int ch = tid + it * 128;
            int row = ch >> 3, c = ch & 7;
            uint32_t dst = stg + (uint32_t)(row * 128) + (uint32_t)((c * 16) ^ ((row & 7) * 16));
            int tok = s_tok[row];
            uint32_t sz = (tok < 0) ? 0u : 16u;
            const __half* src = g_xh + (size_t)(tok < 0 ? 0 : tok) * DIMD + k0 + c * 8;
            cpa16(dst, src, sz);
        }
        #pragma unroll
        for (int it = 0; it < 8; ++it) {      // B: 1024 chunks of 16B
            int ch = tid + it * 128;
            int row = ch >> 3, c = ch & 7;
            uint32_t dst = stg + OFF_B + (uint32_t)(row * 128) + (uint32_t)((c * 16) ^ ((row & 7) * 16));
            const __half* src = g_w1h + ((size_t)e * HIDH + nt * 128 + row) * DIMD + k0 + c * 8;
            cpa16(dst, src, 16u);
        }
        cp_commit();
    };

    const int KC = DIMD / 64;  // 8
    issue(0, 0); issue(1, 1);
    for (int kc = 0; kc < KC; ++kc) {
        if (kc + 2 < KC)       { issue((kc + 2) % 3, kc + 2); cp_wait<2>(); }
        else if (kc + 2 == KC) { cp_wait<1>(); }
        else                   { cp_wait<0>(); }
        __syncthreads();
        chunk64(sb + SM_STAGE + (kc % 3) * STG, ab, axor, acsel, bb, bxor, bcsel, acc);
        __syncthreads();
    }

    // epilogue: +bias, exact GELU, store fp16 hidden (private expert region)
    int r_lo = lane >> 2, cbx = (lane & 3) * 2;
    size_t slot0 = (size_t)e * ECAP + mt * 128;
    const float* b1e = b1 + (size_t)e * HIDH;
    #pragma unroll
    for (int mi = 0; mi < 4; ++mi)
        #pragma unroll
        for (int hh = 0; hh < 2; ++hh) {
            int row = wm * 64 + mi * 16 + hh * 8 + r_lo;
            if (row >= vrows) continue;
            size_t sbase = (slot0 + row) * HIDH;
            #pragma unroll
            for (int ni = 0; ni < 8; ++ni) {
                int col = nt * 128 + wn * 64 + ni * 8 + cbx;
                float v0 = acc[mi][ni][hh * 2 + 0] + b1e[col];
                float v1 = acc[mi][ni][hh * 2 + 1] + b1e[col + 1];
                float q0 = 0.5f * v0 * (1.0f + erff(v0 * 0.70710678118654752f));
                float q1 = 0.5f * v1 * (1.0f + erff(v1 * 0.70710678118654752f));
                *(__half2*)(g_hh + sbase + col) = __floats2half2_rn(q0, q1);
            }
        }
}

// ---------------- GEMM2: Y = H @ W2 + b2; out[tok] += w * Y ----------------
__global__ __launch_bounds__(128, 2) void k_gemm2(const float* __restrict__ b2,
                                                  float* __restrict__ out) {
    int e = blockIdx.z, mt = blockIdx.y, nt = blockIdx.x;
    int cnt = g_cnt[e];
    if (cnt > ECAP) cnt = ECAP;
    if (mt * 128 >= cnt) return;

    uint32_t sb = smem_u32(smc);
    int tid = threadIdx.x, wid = tid >> 5, lane = tid & 31;
    int wm = wid & 1, wn = wid >> 1;
    int* s_tok = (int*)smc;
    float* s_wgt = (float*)(smc + 512);
    {
        int gi = mt * 128 + tid;
        bool ok = gi < cnt;
        s_tok[tid] = ok ? g_tok[e * ECAP + gi] : -1;
        s_wgt[tid] = ok ? g_wgt[e * ECAP + gi] : 0.0f;
    }
    __syncthreads();

    int arow = lane & 15;
    uint32_t acsel = (uint32_t)((lane >> 4) << 4);
    uint32_t axor  = (uint32_t)((arow & 7) * 16);
    uint32_t ab[4];
    #pragma unroll
    for (int mi = 0; mi < 4; ++mi) ab[mi] = (uint32_t)((wm * 64 + mi * 16 + arow) * 128);
    int brow = ((lane >> 4) << 3) + (lane & 7);
    uint32_t bcsel = (uint32_t)(((lane >> 3) & 1) << 4);
    uint32_t bxor  = (uint32_t)((brow & 7) * 16);
    uint32_t bb[4];
    #pragma unroll
    for (int nj = 0; nj < 4; ++nj) bb[nj] = (uint32_t)((wn * 64 + nj * 16 + brow) * 128);

    float acc[4][8][4];
    #pragma unroll
    for (int i = 0; i < 4; ++i)
        #pragma unroll
        for (int j = 0; j < 8; ++j)
            #pragma unroll
            for (int q = 0; q < 4; ++q) acc[i][j][q] = 0.0f;

    auto issue = [&](int buf, int kc2) {
        uint32_t stg = sb + SM_STAGE + buf * STG;
        int k0 = kc2 * 64;
        #pragma unroll
        for (int it = 0; it < 8; ++it) {      // A: hidden fp16 rows (contiguous slots)
            int ch = tid + it * 128;
            int row = ch >> 3, c = ch & 7;
            uint32_t dst = stg + (uint32_t)(row * 128) + (uint32_t)((c * 16) ^ ((row & 7) * 16));
            const __half* src = g_hh + ((size_t)e * ECAP + mt * 128 + row) * HIDH + k0 + c * 8;
            cpa16(dst, src, 16u);
        }
        #pragma unroll
        for (int it = 0; it < 8; ++it) {      // B: W2^T rows
            int ch = tid + it * 128;
            int row = ch >> 3, c = ch & 7;
            uint32_t dst = stg + OFF_B + (uint32_t)(row * 128) + (uint32_t)((c * 16) ^ ((row & 7) * 16));
            const __half* src = g_w2h + ((size_t)e * DIMD + nt * 128 + row) * HIDH + k0 + c * 8;
            cpa16(dst, src, 16u);
        }
        cp_commit();
    };

    const int KC = HIDH / 64;  // 16
    issue(0, 0); issue(1, 1);
    for (int kc = 0; kc < KC; ++kc) {
        if (kc + 2 < KC)       { issue((kc + 2) % 3, kc + 2); cp_wait<2>(); }
        else if (kc + 2 == KC) { cp_wait<1>(); }
        else                   { cp_wait<0>(); }
        __syncthreads();
        chunk64(sb + SM_STAGE + (kc % 3) * STG, ab, axor, acsel, bb, bxor, bcsel, acc);
        __syncthreads();
    }

    // epilogue: +b2, weighted scatter-add into out
    int r_lo = lane >> 2, cbx = (lane & 3) * 2;
    const float* b2e = b2 + (size_t)e * DIMD;
    #pragma unroll
    for (int mi = 0; mi < 4; ++mi)
        #pragma unroll
        for (int hh = 0; hh < 2; ++hh) {
            int row = wm * 64 + mi * 16 + hh * 8 + r_lo;
            int tok = s_tok[row];
            float w = s_wgt[row];
            if (tok < 0 || w == 0.0f) continue;
            float* orow = out + (size_t)tok * DIMD;
            #pragma unroll
            for (int ni = 0; ni < 8; ++ni) {
                int col = nt * 128 + wn * 64 + ni * 8 + cbx;
                float y0 = acc[mi][ni][hh * 2 + 0] + b2e[col];
                float y1 = acc[mi][ni][hh * 2 + 1] + b2e[col + 1];
                atomicAdd(orow + col,     w * y0);
                atomicAdd(orow + col + 1, w * y1);
            }
        }
}

// ---------------- launch ----------------
extern "C" void kernel_launch(void* const* d_in, const int* in_sizes, int n_in,
                              void* d_out, int out_size) {
    const float* x  = (const float*)d_in[0];
    const float* rt = (const float*)d_in[1];
    const float* W1 = (const float*)d_in[2];
    const float* b1 = (const float*)d_in[3];
    const float* W2 = (const float*)d_in[4];
    const float* b2 = (const float*)d_in[5];
    float* out = (float*)d_out;

    cudaFuncSetAttribute(k_gemm1, cudaFuncAttributeMaxDynamicSharedMemorySize, SMEM_DYN);
    cudaFuncSetAttribute(k_gemm2, cudaFuncAttributeMaxDynamicSharedMemorySize, SMEM_DYN);

    dim3 tb(32, 8);
    // order chosen so k_gemm1 is the 4th launch (ncu -s window)
    k_split_x<<<(TOKS * DIMD / 4 + 255) / 256, 256>>>(x, out);  // also zeros out + g_cnt
    k_scatter<<<TOKS / 256, 256>>>(rt);
    k_tsplit<<<dim3(HIDH / 32, DIMD / 32, NEXP), tb>>>(W1, 0, DIMD, HIDH);
    k_gemm1<<<dim3(HIDH / 128, ECAP / 128, NEXP), 128, SMEM_DYN>>>(b1);
    k_tsplit<<<dim3(DIMD / 32, HIDH / 32, NEXP), tb>>>(W2, 1, HIDH, DIMD);
    k_gemm2<<<dim3(DIMD / 128, ECAP / 128, NEXP), 128, SMEM_DYN>>>(b2, out);
}

// round 14
// speedup vs baseline: 1.5654x; 1.0140x over previous
#include <cuda_runtime.h>
#include <cuda_fp16.h>
#include <stdint.h>

#define TOKS 8192
#define DIMD 512
#define HIDH 1024
#define NEXP 16
#define ECAP 2048                    // fixed capacity per expert (mean 1024, >30 sigma)
#define HROWS (NEXP * ECAP)

// ---------------- device scratch ----------------
__device__ int   g_cnt[NEXP];
__device__ int   g_tok[NEXP * ECAP];
__device__ float g_wgt[NEXP * ECAP];
__device__ __align__(256) __half g_xh[TOKS * DIMD];                  // x (fp16)
__device__ __align__(256) __half g_w1h[NEXP * HIDH * DIMD];          // W1^T: [e][h][d] fp16
__device__ __align__(256) __half g_w2h[NEXP * DIMD * HIDH];          // W2^T: [e][dout][h] fp16
__device__ __align__(256) __half g_hh[(size_t)HROWS * HIDH];         // gelu hidden (fp16)

// ---------------- helpers ----------------
__device__ __forceinline__ uint32_t smem_u32(const void* p) {
    uint32_t a;
    asm("{ .reg .u64 t; cvta.to.shared.u64 t, %1; cvt.u32.u64 %0, t; }" : "=r"(a) : "l"(p));
    return a;
}
__device__ __forceinline__ void cpa16(uint32_t dst, const void* src, uint32_t sz) {
    asm volatile("cp.async.cg.shared.global [%0], [%1], 16, %2;"
                 :: "r"(dst), "l"(src), "r"(sz) : "memory");
}
__device__ __forceinline__ void cp_commit() {
    asm volatile("cp.async.commit_group;" ::: "memory");
}
template <int N>
__device__ __forceinline__ void cp_wait() {
    asm volatile("cp.async.wait_group %0;" :: "n"(N) : "memory");
}
__device__ __forceinline__ void ldsm4(uint32_t* r, uint32_t addr) {
    asm volatile("ldmatrix.sync.aligned.m8n8.x4.shared.b16 {%0,%1,%2,%3}, [%4];"
                 : "=r"(r[0]), "=r"(r[1]), "=r"(r[2]), "=r"(r[3]) : "r"(addr));
}
__device__ __forceinline__ void mma_f16(float* d, const uint32_t* a, const uint32_t* b) {
    asm volatile(
        "mma.sync.aligned.m16n8k16.row.col.f32.f16.f16.f32 "
        "{%0,%1,%2,%3}, {%4,%5,%6,%7}, {%8,%9}, {%0,%1,%2,%3};"
        : "+f"(d[0]), "+f"(d[1]), "+f"(d[2]), "+f"(d[3])
        : "r"(a[0]), "r"(a[1]), "r"(a[2]), "r"(a[3]), "r"(b[0]), "r"(b[1]));
}

// smem: s_tok[128] @0, s_wgt[128] @512, 3 stages @1024
// stage (BK=64): A [128 x 128B SW128] @0 ; B [128 x 128B SW128] @16384
// addr = row*128 + ((t) ^ ((row&7)*16))
#define OFF_B    16384
#define STG      32768
#define SM_STAGE 1024
#define SMEM_DYN (SM_STAGE + 3 * STG)   // 99328 (x2 CTAs = 198656 <= 228KB/SM)

extern __shared__ __align__(1024) char smc[];

// ---------------- prep kernels ----------------
// also zeroes `out` (same float4 index space: TOKS*DIMD) and g_cnt
__global__ void k_split_x(const float* __restrict__ x, float* __restrict__ out) {
    if (blockIdx.x == 0 && threadIdx.x < NEXP) g_cnt[threadIdx.x] = 0;
    int i = blockIdx.x * 256 + threadIdx.x;
    if (i < TOKS * DIMD / 4) {
        float4 v = ((const float4*)x)[i];
        ((__half2*)g_xh)[i * 2]     = __floats2half2_rn(v.x, v.y);
        ((__half2*)g_xh)[i * 2 + 1] = __floats2half2_rn(v.z, v.w);
        ((float4*)out)[i] = make_float4(0.f, 0.f, 0.f, 0.f);
    }
}

__global__ void k_scatter(const float* __restrict__ rt) {
    __shared__ int s_cnt[NEXP], s_base[NEXP];
    int tid = threadIdx.x;
    int n = blockIdx.x * 256 + tid;
    if (tid < NEXP) s_cnt[tid] = 0;
    __syncthreads();
    float v[NEXP];
    const float4* r4 = (const float4*)(rt + (size_t)n * NEXP);
    float4 a = r4[0], b = r4[1], c = r4[2], d = r4[3];
    v[0]=a.x; v[1]=a.y; v[2]=a.z; v[3]=a.w; v[4]=b.x; v[5]=b.y; v[6]=b.z; v[7]=b.w;
    v[8]=c.x; v[9]=c.y; v[10]=c.z; v[11]=c.w; v[12]=d.x; v[13]=d.y; v[14]=d.z; v[15]=d.w;
    int le[4]; float lv[4]; int ls[4]; int k = 0;
    #pragma unroll
    for (int e = 0; e < NEXP; ++e)
        if (v[e] > 0.0f && k < 4) { le[k] = e; lv[k] = v[e]; ls[k] = atomicAdd(&s_cnt[e], 1); ++k; }
    __syncthreads();
    if (tid < NEXP) s_base[tid] = atomicAdd(&g_cnt[tid], s_cnt[tid]);
    __syncthreads();
    for (int j = 0; j < k; ++j) {
        int slot = s_base[le[j]] + ls[j];
        if (slot < ECAP) { g_tok[le[j] * ECAP + slot] = n; g_wgt[le[j] * ECAP + slot] = lv[j]; }
    }
}

// transpose + fp16 convert: W [e][R][C] (C contig) -> T [e][C][R]
__global__ void k_tsplit(const float* __restrict__ W, int which, int R, int C) {
    __shared__ float tile[32][33];
    int e = blockIdx.z, c0 = blockIdx.x * 32, r0 = blockIdx.y * 32;
    const float* We = W + (size_t)e * R * C;
    int tx = threadIdx.x, ty = threadIdx.y;
    for (int i = ty; i < 32; i += 8)
        tile[i][tx] = We[(size_t)(r0 + i) * C + c0 + tx];
    __syncthreads();
    __half* Th = (which ? g_w2h : g_w1h) + (size_t)e * R * C;
    int tid = ty * 32 + tx;
    #pragma unroll
    for (int w = tid; w < 512; w += 256) {
        int c = w >> 4, rp = (w & 15) * 2;
        size_t o = (size_t)(c0 + c) * R + r0 + rp;
        *(__half2*)(Th + o) = __floats2half2_rn(tile[rp][c], tile[rp + 1][c]);
    }
}

// ---------------- BK=64 chunk compute ----------------
// CTA 128x128, 8 warps: wm = wid&3 (32 rows), wn = wid>>2 (64 cols)
__device__ __forceinline__ void chunk64(
    uint32_t stg,
    uint32_t ab0, uint32_t ab1, uint32_t axor, uint32_t acsel,
    uint32_t bb0, uint32_t bb1, uint32_t bb2, uint32_t bb3,
    uint32_t bxor, uint32_t bcsel, float acc[2][8][4])
{
    #pragma unroll
    for (int ks = 0; ks < 4; ++ks) {
        uint32_t ta = ((uint32_t)(ks * 32) + acsel) ^ axor;
        uint32_t tb = ((uint32_t)(ks * 32) + bcsel) ^ bxor;
        uint32_t a0[4], a1[4], bh[4][4];
        ldsm4(a0, stg + ab0 + ta);
        ldsm4(a1, stg + ab1 + ta);
        ldsm4(bh[0], stg + OFF_B + bb0 + tb);
        ldsm4(bh[1], stg + OFF_B + bb1 + tb);
        ldsm4(bh[2], stg + OFF_B + bb2 + tb);
        ldsm4(bh[3], stg + OFF_B + bb3 + tb);
        #pragma unroll
        for (int np = 0; np < 4; ++np) {
            mma_f16(acc[0][np * 2],     a0, &bh[np][0]);
            mma_f16(acc[0][np * 2 + 1], a0, &bh[np][2]);
            mma_f16(acc[1][np * 2],     a1, &bh[np][0]);
            mma_f16(acc[1][np * 2 + 1], a1, &bh[np][2]);
        }
    }
}

// ---------------- GEMM1: H = gelu(Xg @ W1 + b1) -> fp16 ----------------
__global__ __launch_bounds__(256, 2) void k_gemm1(const float* __restrict__ b1) {
    int e = blockIdx.z, mt = blockIdx.y, nt = blockIdx.x;
    int cnt = g_cnt[e];
    if (cnt > ECAP) cnt = ECAP;
    if (mt * 128 >= cnt) return;
    int vrows = cnt - mt * 128;
    if (vrows > 128) vrows = 128;

    uint32_t sb = smem_u32(smc);
    int tid = threadIdx.x, wid = tid >> 5, lane = tid & 31;
    int wm = wid & 3, wn = wid >> 2;
    int* s_tok = (int*)smc;
    if (tid < 128) {
        int gi = mt * 128 + tid;
        s_tok[tid] = (gi < cnt) ? g_tok[e * ECAP + gi] : -1;
    }
    __syncthreads();

    int arow = lane & 15;
    uint32_t acsel = (uint32_t)((lane >> 4) << 4);
    uint32_t axor  = (uint32_t)((arow & 7) * 16);
    uint32_t ab0 = (uint32_t)((wm * 32 + arow) * 128);
    uint32_t ab1 = (uint32_t)((wm * 32 + 16 + arow) * 128);
    int brow = ((lane >> 4) << 3) + (lane & 7);
    uint32_t bcsel = (uint32_t)(((lane >> 3) & 1) << 4);
    uint32_t bxor  = (uint32_t)((brow & 7) * 16);
    uint32_t bb0 = (uint32_t)((wn * 64 +  0 + brow) * 128);
    uint32_t bb1 = (uint32_t)((wn * 64 + 16 + brow) * 128);
    uint32_t bb2 = (uint32_t)((wn * 64 + 32 + brow) * 128);
    uint32_t bb3 = (uint32_t)((wn * 64 + 48 + brow) * 128);

    float acc[2][8][4];
    #pragma unroll
    for (int i = 0; i < 2; ++i)
        #pragma unroll
        for (int j = 0; j < 8; ++j)
            #pragma unroll
            for (int q = 0; q < 4; ++q) acc[i][j][q] = 0.0f;

    auto issue = [&](int buf, int kc2) {
        uint32_t stg = sb + SM_STAGE + buf * STG;
        int k0 = kc2 * 64;
        #pragma unroll
        for (int it = 0; it < 4; ++it) {      // A: 1024 chunks of 16B (gather)
            int ch = tid + it * 256;
            int row = ch >> 3, c = ch & 7;
            uint32_t dst = stg + (uint32_t)(row * 128) + (uint32_t)((c * 16) ^ ((row & 7) * 16));
            int tok = s_tok[row];
            uint32_t sz = (tok < 0) ? 0u : 16u;
            const __half* src = g_xh + (size_t)(tok < 0 ? 0 : tok) * DIMD + k0 + c * 8;
            cpa16(dst, src, sz);
        }
        #pragma unroll
        for (int it = 0; it < 4; ++it) {      // B: 1024 chunks of 16B
            int ch = tid + it * 256;
            int row = ch >> 3, c = ch & 7;
            uint32_t dst = stg + OFF_B + (uint32_t)(row * 128) + (uint32_t)((c * 16) ^ ((row & 7) * 16));
            const __half* src = g_w1h + ((size_t)e * HIDH + nt * 128 + row) * DIMD + k0 + c * 8;
            cpa16(dst, src, 16u);
        }
        cp_commit();
    };

    const int KC = DIMD / 64;  // 8
    issue(0, 0); issue(1, 1);
    // single-sync mainloop: wait -> sync -> compute -> issue(k+2)
    // safety: any overwrite of stage k%3 (= issue k+3) happens after the
    // top-of-iter-(k+1) sync, which requires all warps done with compute k.
    for (int kc = 0; kc < KC; ++kc) {
        if (kc + 1 < KC) cp_wait<1>(); else cp_wait<0>();
        __syncthreads();
        chunk64(sb + SM_STAGE + (kc % 3) * STG,
                ab0, ab1, axor, acsel, bb0, bb1, bb2, bb3, bxor, bcsel, acc);
        if (kc + 2 < KC) issue((kc + 2) % 3, kc + 2);
    }

    // epilogue: +bias, exact GELU, store fp16 hidden (private expert region)
    int r_lo = lane >> 2, cbx = (lane & 3) * 2;
    size_t slot0 = (size_t)e * ECAP + mt * 128;
    const float* b1e = b1 + (size_t)e * HIDH;
    #pragma unroll
    for (int mi = 0; mi < 2; ++mi)
        #pragma unroll
        for (int hh = 0; hh < 2; ++hh) {
            int row = wm * 32 + mi * 16 + hh * 8 + r_lo;
            if (row >= vrows) continue;
            size_t sbase = (slot0 + row) * HIDH;
            #pragma unroll
            for (int ni = 0; ni < 8; ++ni) {
                int col = nt * 128 + wn * 64 + ni * 8 + cbx;
                float v0 = acc[mi][ni][hh * 2 + 0] + b1e[col];
                float v1 = acc[mi][ni][hh * 2 + 1] + b1e[col + 1];
                float q0 = 0.5f * v0 * (1.0f + erff(v0 * 0.70710678118654752f));
                float q1 = 0.5f * v1 * (1.0f + erff(v1 * 0.70710678118654752f));
                *(__half2*)(g_hh + sbase + col) = __floats2half2_rn(q0, q1);
            }
        }
}

// ---------------- GEMM2: Y = H @ W2 + b2; out[tok] += w * Y ----------------
__global__ __launch_bounds__(256, 2) void k_gemm2(const float* __restrict__ b2,
                                                  float* __restrict__ out) {
    int e = blockIdx.z, mt = blockIdx.y, nt = blockIdx.x;
    int cnt = g_cnt[e];
    if (cnt > ECAP) cnt = ECAP;
    if (mt * 128 >= cnt) return;

    uint32_t sb = smem_u32(smc);
    int tid = threadIdx.x, wid = tid >> 5, lane = tid & 31;
    int wm = wid & 3, wn = wid >> 2;
    int* s_tok = (int*)smc;
    float* s_wgt = (float*)(smc + 512);
    if (tid < 128) {
        int gi = mt * 128 + tid;
        bool ok = gi < cnt;
        s_tok[tid] = ok ? g_tok[e * ECAP + gi] : -1;
        s_wgt[tid] = ok ? g_wgt[e * ECAP + gi] : 0.0f;
    }
    __syncthreads();

    int arow = lane & 15;
    uint32_t acsel = (uint32_t)((lane >> 4) << 4);
    uint32_t axor  = (uint32_t)((arow & 7) * 16);
    uint32_t ab0 = (uint32_t)((wm * 32 + arow) * 128);
    uint32_t ab1 = (uint32_t)((wm * 32 + 16 + arow) * 128);
    int brow = ((lane >> 4) << 3) + (lane & 7);
    uint32_t bcsel = (uint32_t)(((lane >> 3) & 1) << 4);
    uint32_t bxor  = (uint32_t)((brow & 7) * 16);
    uint32_t bb0 = (uint32_t)((wn * 64 +  0 + brow) * 128);
    uint32_t bb1 = (uint32_t)((wn * 64 + 16 + brow) * 128);
    uint32_t bb2 = (uint32_t)((wn * 64 + 32 + brow) * 128);
    uint32_t bb3 = (uint32_t)((wn * 64 + 48 + brow) * 128);

    float acc[2][8][4];
    #pragma unroll
    for (int i = 0; i < 2; ++i)
        #pragma unroll
        for (int j = 0; j < 8; ++j)
            #pragma unroll
            for (int q = 0; q < 4; ++q) acc[i][j][q] = 0.0f;

    auto issue = [&](int buf, int kc2) {
        uint32_t stg = sb + SM_STAGE + buf * STG;
        int k0 = kc2 * 64;
        #pragma unroll
        for (int it = 0; it < 4; ++it) {      // A: hidden fp16 rows (contiguous slots)
            int ch = tid + it * 256;
            int row = ch >> 3, c = ch & 7;
            uint32_t dst = stg + (uint32_t)(row * 128) + (uint32_t)((c * 16) ^ ((row & 7) * 16));
            const __half* src = g_hh + ((size_t)e * ECAP + mt * 128 + row) * HIDH + k0 + c * 8;
            cpa16(dst, src, 16u);
        }
        #pragma unroll
        for (int it = 0; it < 4; ++it) {      // B: W2^T rows
            int ch = tid + it * 256;
            int row = ch >> 3, c = ch & 7;
            uint32_t dst = stg + OFF_B + (uint32_t)(row * 128) + (uint32_t)((c * 16) ^ ((row & 7) * 16));
            const __half* src = g_w2h + ((size_t)e * DIMD + nt * 128 + row) * HIDH + k0 + c * 8;
            cpa16(dst, src, 16u);
        }
        cp_commit();
    };

    const int KC = HIDH / 64;  // 16
    issue(0, 0); issue(1, 1);
    for (int kc = 0; kc < KC; ++kc) {
        if (kc + 1 < KC) cp_wait<1>(); else cp_wait<0>();
        __syncthreads();
        chunk64(sb + SM_STAGE + (kc % 3) * STG,
                ab0, ab1, axor, acsel, bb0, bb1, bb2, bb3, bxor, bcsel, acc);
        if (kc + 2 < KC) issue((kc + 2) % 3, kc + 2);
    }

    // epilogue: +b2, weighted scatter-add into out
    int r_lo = lane >> 2, cbx = (lane & 3) * 2;
    const float* b2e = b2 + (size_t)e * DIMD;
    #pragma unroll
    for (int mi = 0; mi < 2; ++mi)
        #pragma unroll
        for (int hh = 0; hh < 2; ++hh) {
            int row = wm * 32 + mi * 16 + hh * 8 + r_lo;
            int tok = s_tok[row];
            float w = s_wgt[row];
            if (tok < 0 || w == 0.0f) continue;
            float* orow = out + (size_t)tok * DIMD;
            #pragma unroll
            for (int ni = 0; ni < 8; ++ni) {
                int col = nt * 128 + wn * 64 + ni * 8 + cbx;
                float y0 = acc[mi][ni][hh * 2 + 0] + b2e[col];
                float y1 = acc[mi][ni][hh * 2 + 1] + b2e[col + 1];
                atomicAdd(orow + col,     w * y0);
                atomicAdd(orow + col + 1, w * y1);
            }
        }
}

// ---------------- launch ----------------
extern "C" void kernel_launch(void* const* d_in, const int* in_sizes, int n_in,
                              void* d_out, int out_size) {
    const float* x  = (const float*)d_in[0];
    const float* rt = (const float*)d_in[1];
    const float* W1 = (const float*)d_in[2];
    const float* b1 = (const float*)d_in[3];
    const float* W2 = (const float*)d_in[4];
    const float* b2 = (const float*)d_in[5];
    float* out = (float*)d_out;

    // one-time host objects (no device memory)
    static cudaStream_t s2 = nullptr;
    static cudaEvent_t evFork = nullptr, evJoin = nullptr;
    if (!s2) {
        cudaStreamCreateWithFlags(&s2, cudaStreamNonBlocking);
        cudaEventCreateWithFlags(&evFork, cudaEventDisableTiming);
        cudaEventCreateWithFlags(&evJoin, cudaEventDisableTiming);
        cudaFuncSetAttribute(k_gemm1, cudaFuncAttributeMaxDynamicSharedMemorySize, SMEM_DYN);
        cudaFuncSetAttribute(k_gemm2, cudaFuncAttributeMaxDynamicSharedMemorySize, SMEM_DYN);
    }

    dim3 tb(32, 8);
    // fork: tsplit(W2) runs on s2 concurrently with the gemm1 chain
    cudaEventRecord(evFork, 0);
    cudaStreamWaitEvent(s2, evFork, 0);
    k_tsplit<<<dim3(DIMD / 32, HIDH / 32, NEXP), tb, 0, s2>>>(W2, 1, HIDH, DIMD);
    cudaEventRecord(evJoin, s2);

    // main chain on legacy stream (k_gemm1 is 4th launch for ncu window)
    k_split_x<<<(TOKS * DIMD / 4 + 255) / 256, 256>>>(x, out);  // also zeros out + g_cnt
    k_scatter<<<TOKS / 256, 256>>>(rt);
    k_tsplit<<<dim3(HIDH / 32, DIMD / 32, NEXP), tb>>>(W1, 0, DIMD, HIDH);
    k_gemm1<<<dim3(HIDH / 128, ECAP / 128, NEXP), 256, SMEM_DYN>>>(b1);

    // join: gemm2 needs W2^T
    cudaStreamWaitEvent(0, evJoin, 0);
    k_gemm2<<<dim3(DIMD / 128, ECAP / 128, NEXP), 256, SMEM_DYN>>>(b2, out);
}